// round 13
// baseline (speedup 1.0000x reference)
#include <cuda_runtime.h>
#include <mma.h>
#include <cuda_fp16.h>
#include <math.h>

using namespace nvcuda;

#define BB 8
#define CC 128
#define HH 128
#define WW 128
#define NHH 4
#define HDD 32
#define SG2 256
#define HWP (HH*WW)      // 16384
#define NPIX (BB*HWP)    // 131072
#define KK2 25
#define SCALE 0.17677669529663687f   // 1/sqrt(32)

// ---- scratch (static device arrays; no runtime allocation) ----
static __device__ __align__(16) __half g_q[(size_t)NPIX*CC];
static __device__ __align__(16) __half g_k[(size_t)NPIX*CC];
static __device__ __align__(16) __half g_v[(size_t)NPIX*CC];
static __device__ __align__(16) __half g_agg[(size_t)NPIX*CC];
static __device__ __align__(16) __half g_pwd[(size_t)NPIX*KK2];  // x256 scale (cancels)

#define LDH 136    // fp16 smem row stride for GEMMs (halfs)
#define SLD 40     // fp16 smem row stride for stencils (halfs) — 80 B = 5*16

__device__ __forceinline__ uint2 f4toh4(float4 v) {
    __half2 lo = __floats2half2_rn(v.x, v.y);
    __half2 hi = __floats2half2_rn(v.z, v.w);
    uint2 r;
    r.x = *(unsigned*)&lo;
    r.y = *(unsigned*)&hi;
    return r;
}

__device__ __forceinline__ float dot32v(const __half2* q2,
        uint4 r0, uint4 r1, uint4 r2, uint4 r3)
{
    __half2 a2 = __float2half2_rn(0.f);
    __half2 b2 = __float2half2_rn(0.f);
    a2 = __hfma2(q2[0],  *(__half2*)&r0.x, a2);
    b2 = __hfma2(q2[1],  *(__half2*)&r0.y, b2);
    a2 = __hfma2(q2[2],  *(__half2*)&r0.z, a2);
    b2 = __hfma2(q2[3],  *(__half2*)&r0.w, b2);
    a2 = __hfma2(q2[4],  *(__half2*)&r1.x, a2);
    b2 = __hfma2(q2[5],  *(__half2*)&r1.y, b2);
    a2 = __hfma2(q2[6],  *(__half2*)&r1.z, a2);
    b2 = __hfma2(q2[7],  *(__half2*)&r1.w, b2);
    a2 = __hfma2(q2[8],  *(__half2*)&r2.x, a2);
    b2 = __hfma2(q2[9],  *(__half2*)&r2.y, b2);
    a2 = __hfma2(q2[10], *(__half2*)&r2.z, a2);
    b2 = __hfma2(q2[11], *(__half2*)&r2.w, b2);
    a2 = __hfma2(q2[12], *(__half2*)&r3.x, a2);
    b2 = __hfma2(q2[13], *(__half2*)&r3.y, b2);
    a2 = __hfma2(q2[14], *(__half2*)&r3.z, a2);
    b2 = __hfma2(q2[15], *(__half2*)&r3.w, b2);
    float2 fa = __half22float2(a2);
    float2 fb = __half22float2(b2);
    return (fa.x + fa.y) + (fb.x + fb.y);
}

__device__ __forceinline__ void fma16(__half2* o, __half2 wk2, uint4 r0, uint4 r1)
{
    o[0] = __hfma2(wk2, *(__half2*)&r0.x, o[0]);
    o[1] = __hfma2(wk2, *(__half2*)&r0.y, o[1]);
    o[2] = __hfma2(wk2, *(__half2*)&r0.z, o[2]);
    o[3] = __hfma2(wk2, *(__half2*)&r0.w, o[3]);
    o[4] = __hfma2(wk2, *(__half2*)&r1.x, o[4]);
    o[5] = __hfma2(wk2, *(__half2*)&r1.y, o[5]);
    o[6] = __hfma2(wk2, *(__half2*)&r1.z, o[6]);
    o[7] = __hfma2(wk2, *(__half2*)&r1.w, o[7]);
}

// ============================================================
// Kernel 1: QKV GEMM — one N-tile per block (gridDim.y = 3),
// single __syncthreads, A restaged per block (x is L2-resident).
// ============================================================
#define QKV_SMEM (16*132*4 + 2*128*LDH*2)   // 78080 B -> 2 blocks/SM

__global__ void __launch_bounds__(256, 2)
k_qkv_wmma(const float* __restrict__ x, const float* __restrict__ w_qk,
           const float* __restrict__ b_qk, const float* __restrict__ w_v,
           const float* __restrict__ b_v)
{
    extern __shared__ char smraw[];
    float*  bias_s = (float*)smraw;                    // [16][132]
    __half* As     = (__half*)(smraw + 16*132*4);      // [k=128][m=128] ld LDH
    __half* Bs     = As + 128*LDH;                     // [k=128][n=128] ld LDH

    const int tid = threadIdx.x;
    const int wid = tid >> 5;
    const int wm  = wid & 3;
    const int wn  = wid >> 2;
    const int nt  = blockIdx.y;          // 0:q 1:k 2:v
    const int p0  = blockIdx.x * 128;
    const int b   = p0 / HWP;
    const int ij0 = p0 % HWP;
    const float* xb = x + (size_t)b*CC*HWP + ij0;

#pragma unroll
    for (int it = 0; it < 16; it++) {
        int idx = tid + it*256;
        int k = idx >> 5, m4 = idx & 31;
        *(uint2*)(As + k*LDH + m4*4) =
            f4toh4(*(const float4*)(xb + (size_t)k*HWP + m4*4));
    }
#pragma unroll
    for (int it = 0; it < 16; it++) {
        int idx = tid + it*256;
        int k = idx >> 5, n4 = idx & 31;
        const float* src = (nt < 2) ? (w_qk + k*2*CC + nt*128 + n4*4)
                                    : (w_v  + k*CC  + n4*4);
        *(uint2*)(Bs + k*LDH + n4*4) = f4toh4(*(const float4*)src);
    }
    if (tid < 128) {
        float bv = (nt < 2) ? b_qk[nt*128 + tid] : b_v[tid];
#pragma unroll
        for (int r = 0; r < 16; r++) bias_s[r*132 + tid] = bv;
    }
    __syncthreads();

    wmma::fragment<wmma::accumulator, 16,16,16, float> acc[2][4];
#pragma unroll
    for (int mi = 0; mi < 2; mi++)
#pragma unroll
        for (int ni = 0; ni < 4; ni++)
            wmma::load_matrix_sync(acc[mi][ni], bias_s + wn*64 + ni*16,
                                   132, wmma::mem_row_major);

#pragma unroll
    for (int k0 = 0; k0 < CC; k0 += 16) {
        wmma::fragment<wmma::matrix_a, 16,16,16, __half, wmma::col_major> a[2];
#pragma unroll
        for (int mi = 0; mi < 2; mi++)
            wmma::load_matrix_sync(a[mi], As + k0*LDH + wm*32 + mi*16, LDH);
        wmma::fragment<wmma::matrix_b, 16,16,16, __half, wmma::row_major> bf[4];
#pragma unroll
        for (int ni = 0; ni < 4; ni++)
            wmma::load_matrix_sync(bf[ni], Bs + k0*LDH + wn*64 + ni*16, LDH);
#pragma unroll
        for (int mi = 0; mi < 2; mi++)
#pragma unroll
            for (int ni = 0; ni < 4; ni++)
                wmma::mma_sync(acc[mi][ni], a[mi], bf[ni], acc[mi][ni]);
    }

    __half* dstbase = (nt == 0) ? g_q : (nt == 1) ? g_k : g_v;
#pragma unroll
    for (int mi = 0; mi < 2; mi++)
#pragma unroll
        for (int ni = 0; ni < 4; ni++) {
            wmma::fragment<wmma::accumulator, 16,16,16, __half> hacc;
#pragma unroll
            for (int e = 0; e < 8; e++)
                hacc.x[e] = __float2half(acc[mi][ni].x[e]);
            int n0 = wn*64 + ni*16;
            int head = n0 >> 5, d0 = n0 & 31;
            __half* dst = dstbase +
                ((size_t)(b*NHH + head)*HWP + ij0 + wm*32 + mi*16)*HDD + d0;
            wmma::store_matrix_sync(dst, hacc, HDD, wmma::mem_row_major);
        }
}

// ============================================================
// Kernel 2: pwd, pixel-paired + XOR chunk rotation. (R12-proven.)
// ============================================================
#define PWD_SMEM (432*SLD*2)   // 34560 B

__global__ void __launch_bounds__(128, 4)
k_pwd(const float* __restrict__ sims)
{
    extern __shared__ __half Sh[];  // [432][40]
    const int b  = blockIdx.z;
    const int i0 = blockIdx.y * 8;
    const int j0 = blockIdx.x * 32;
    const int tx = threadIdx.x;     // 0..15
    const int ty = threadIdx.y;     // 0..7
    const int tid = ty*16 + tx;
    const int rot = (tx >> 2) & 1;
    const float* sb = sims + (size_t)b*HWP*SG2;

    float acc0[KK2], acc1[KK2];
#pragma unroll
    for (int k=0;k<KK2;k++) { acc0[k]=0.f; acc1[k]=0.f; }

    for (int scc = 0; scc < SG2; scc += 32) {
        __syncthreads();
        for (int idx = tid; idx < 432*4; idx += 128) {
            int pix = idx >> 2, v = idx & 3;
            int hr = pix / 36, hc = pix - hr*36;
            int gi = i0 - 2 + hr, gj = j0 - 2 + hc;
            uint4 o = make_uint4(0,0,0,0);
            if ((unsigned)gi < HH && (unsigned)gj < WW) {
                const float* src = sb + ((size_t)gi*WW + gj)*SG2 + scc + v*8;
                float4 f0 = *(const float4*)src;
                float4 f1 = *(const float4*)(src + 4);
                f0.x*=16.f; f0.y*=16.f; f0.z*=16.f; f0.w*=16.f;
                f1.x*=16.f; f1.y*=16.f; f1.z*=16.f; f1.w*=16.f;
                uint2 h0 = f4toh4(f0), h1 = f4toh4(f1);
                o = make_uint4(h0.x, h0.y, h1.x, h1.y);
            }
            *(uint4*)(Sh + pix*SLD + v*8) = o;
        }
        __syncthreads();

        __half2 oa[16], ob[16];
        {
            const __half* p0 = Sh + ((ty+2)*36 + (2*tx+2))*SLD;
#pragma unroll
            for (int v=0; v<4; v++) {
                uint4 r = *(const uint4*)(p0 + ((v^rot)<<3));
                oa[v*4+0]=*(__half2*)&r.x; oa[v*4+1]=*(__half2*)&r.y;
                oa[v*4+2]=*(__half2*)&r.z; oa[v*4+3]=*(__half2*)&r.w;
                uint4 s = *(const uint4*)(p0 + SLD + ((v^rot)<<3));
                ob[v*4+0]=*(__half2*)&s.x; ob[v*4+1]=*(__half2*)&s.y;
                ob[v*4+2]=*(__half2*)&s.z; ob[v*4+3]=*(__half2*)&s.w;
            }
        }
#pragma unroll
        for (int di=0; di<5; di++) {
#pragma unroll
            for (int djc=0; djc<6; djc++) {
                const __half* np = Sh + ((ty+di)*36 + (2*tx+djc))*SLD;
                uint4 r0 = *(const uint4*)(np + ((0^rot)<<3));
                uint4 r1 = *(const uint4*)(np + ((1^rot)<<3));
                uint4 r2 = *(const uint4*)(np + ((2^rot)<<3));
                uint4 r3 = *(const uint4*)(np + ((3^rot)<<3));
                if (djc < 5) acc0[di*5+djc]   += dot32v(oa, r0,r1,r2,r3);
                if (djc > 0) acc1[di*5+djc-1] += dot32v(ob, r0,r1,r2,r3);
            }
        }
    }
    const size_t p = (size_t)b*HWP + (size_t)(i0+ty)*WW + (j0+2*tx);
#pragma unroll
    for (int k=0;k<KK2;k++) {
        g_pwd[p*KK2 + k]     = __float2half(acc0[k]);
        g_pwd[(p+1)*KK2 + k] = __float2half(acc1[k]);
    }
}

// ============================================================
// Kernel 3: attention + V agg — dual K/V buffers staged together
// (loads fully overlapped), ONE sync, then scores + V-agg.
// Pixel-paired + XOR chunk rotation.
// ============================================================
#define ATT_SMEM (2*432*SLD*2)   // 69120 B -> 3 blocks/SM

__global__ void __launch_bounds__(128, 3)
k_attn()
{
    extern __shared__ __half Hs[];
    __half* Kh = Hs;                 // [432][40]
    __half* Vh = Hs + 432*SLD;       // [432][40]

    const int bh = blockIdx.z;
    const int b  = bh >> 2;
    const int h  = bh & 3;
    const int i0 = blockIdx.y * 8;
    const int j0 = blockIdx.x * 32;
    const int tx = threadIdx.x;     // 0..15
    const int ty = threadIdx.y;     // 0..7
    const int tid = ty*16 + tx;
    const int rot = (tx >> 2) & 1;
    const size_t headoff = (size_t)bh*HWP*HDD;
    const int ij0 = (i0+ty)*WW + (j0 + 2*tx);

    // ---- stage K and V together (all loads in flight) ----
    const __half* kb = g_k + headoff;
    const __half* vb = g_v + headoff;
    for (int idx = tid; idx < 432*4; idx += 128) {
        int pix = idx >> 2, v = idx & 3;
        int hr = pix / 36, hc = pix - hr*36;
        int gi = i0 - 2 + hr, gj = j0 - 2 + hc;
        uint4 kp = make_uint4(0,0,0,0), vp = make_uint4(0,0,0,0);
        if ((unsigned)gi < HH && (unsigned)gj < WW) {
            size_t off = (size_t)(gi*WW + gj)*HDD + v*8;
            kp = *(const uint4*)(kb + off);
            vp = *(const uint4*)(vb + off);
        }
        *(uint4*)(Kh + pix*SLD + v*8) = kp;
        *(uint4*)(Vh + pix*SLD + v*8) = vp;
    }

    // q pair, loaded from global in permuted chunk order
    __half2 qa[16], qb[16];
    {
        const __half* qp = g_q + headoff + (size_t)ij0*HDD;
#pragma unroll
        for (int v=0; v<4; v++) {
            uint4 r = *(const uint4*)(qp + ((v^rot)<<3));
            qa[v*4+0]=*(__half2*)&r.x; qa[v*4+1]=*(__half2*)&r.y;
            qa[v*4+2]=*(__half2*)&r.z; qa[v*4+3]=*(__half2*)&r.w;
            uint4 s = *(const uint4*)(qp + HDD + ((v^rot)<<3));
            qb[v*4+0]=*(__half2*)&s.x; qb[v*4+1]=*(__half2*)&s.y;
            qb[v*4+2]=*(__half2*)&s.z; qb[v*4+3]=*(__half2*)&s.w;
        }
    }
    __syncthreads();   // the only block-wide sync

    // ---- scores for the pair; weights packed half2 immediately ----
    const __half* pwp = g_pwd + ((size_t)b*HWP + ij0)*KK2;
    __half2 wh2[KK2];
    float ssum0 = 0.f, ssum1 = 0.f;
#pragma unroll
    for (int di=0; di<5; di++) {
#pragma unroll
        for (int djc=0; djc<6; djc++) {
            const __half* np = Kh + ((ty+di)*36 + (2*tx+djc))*SLD;
            uint4 r0 = *(const uint4*)(np + ((0^rot)<<3));
            uint4 r1 = *(const uint4*)(np + ((1^rot)<<3));
            uint4 r2 = *(const uint4*)(np + ((2^rot)<<3));
            uint4 r3 = *(const uint4*)(np + ((3^rot)<<3));
            if (djc < 5) {
                int kk = di*5+djc;
                float s = dot32v(qa, r0,r1,r2,r3);
                float w0 = __expf(s * SCALE) * __half2float(pwp[kk]);
                ssum0 += w0;
                wh2[kk] = __halves2half2(__float2half(w0), __float2half(0.f));
            }
            if (djc > 0) {
                int kk = di*5+djc-1;
                float s = dot32v(qb, r0,r1,r2,r3);
                float w1 = __expf(s * SCALE) * __half2float(pwp[KK2+kk]);
                ssum1 += w1;
                wh2[kk] = __halves2half2(__low2half(wh2[kk]), __float2half(w1));
            }
        }
    }
    {
        __half2 inv2 = __floats2half2_rn(1.f / fmaxf(ssum0, 1e-30f),
                                         1.f / fmaxf(ssum1, 1e-30f));
#pragma unroll
        for (int k=0;k<KK2;k++) wh2[k] = __hmul2(wh2[k], inv2);
    }

    // ---- V aggregation: two channel-halves, chunk-rotated loads ----
    __half* ag = g_agg + ((size_t)b*HWP + ij0)*CC + h*HDD;
#pragma unroll
    for (int ch = 0; ch < 2; ch++) {
        float out0[16], out1[16];
#pragma unroll
        for (int j=0;j<16;j++) { out0[j]=0.f; out1[j]=0.f; }
#pragma unroll
        for (int di=0; di<5; di++) {
            __half2 oa[8], ob[8];
#pragma unroll
            for (int j=0;j<8;j++) { oa[j]=__float2half2_rn(0.f); ob[j]=__float2half2_rn(0.f); }
#pragma unroll
            for (int djc=0; djc<6; djc++) {
                const __half* np = Vh + ((ty+di)*36 + (2*tx+djc))*SLD + ch*16;
                uint4 r0 = *(const uint4*)(np + ((0^rot)<<3));
                uint4 r1 = *(const uint4*)(np + ((1^rot)<<3));
                if (djc < 5) fma16(oa, __low2half2 (wh2[di*5+djc]),   r0, r1);
                if (djc > 0) fma16(ob, __high2half2(wh2[di*5+djc-1]), r0, r1);
            }
#pragma unroll
            for (int j=0;j<8;j++) {
                float2 fa = __half22float2(oa[j]);
                float2 fb = __half22float2(ob[j]);
                out0[2*j] += fa.x; out0[2*j+1] += fa.y;
                out1[2*j] += fb.x; out1[2*j+1] += fb.y;
            }
        }
        // slot v holds chunk v^rot (ch*16 is a whole-chunk offset, rot within half)
#pragma unroll
        for (int v=0; v<2; v++) {
            uint2 h0 = f4toh4(make_float4(out0[v*8+0],out0[v*8+1],out0[v*8+2],out0[v*8+3]));
            uint2 h1 = f4toh4(make_float4(out0[v*8+4],out0[v*8+5],out0[v*8+6],out0[v*8+7]));
            *(uint4*)(ag + ch*16 + ((v^rot)<<3)) = make_uint4(h0.x,h0.y,h1.x,h1.y);
            uint2 g0 = f4toh4(make_float4(out1[v*8+0],out1[v*8+1],out1[v*8+2],out1[v*8+3]));
            uint2 g1 = f4toh4(make_float4(out1[v*8+4],out1[v*8+5],out1[v*8+6],out1[v*8+7]));
            *(uint4*)(ag + CC + ch*16 + ((v^rot)<<3)) = make_uint4(g0.x,g0.y,g1.x,g1.y);
        }
    }
}

// ============================================================
// Kernel 4: proj GEMM via WMMA fp16 + free BCHW transpose store.
// (R10-proven, unchanged.)
// ============================================================
#define PRJ_SMEM (16*132*4 + 2*128*LDH*2)   // 78080 B -> 2 blocks/SM

__global__ void __launch_bounds__(256, 2)
k_proj_wmma(const float* __restrict__ w_proj, const float* __restrict__ b_proj,
            float* __restrict__ out)
{
    extern __shared__ char smraw[];
    float*  bias_s = (float*)smraw;                    // [16][132]
    __half* As     = (__half*)(smraw + 16*132*4);      // [m=128][k=128] ld LDH
    __half* Bs     = As + 128*LDH;                     // [k=128][n=128] ld LDH

    const int tid = threadIdx.x;
    const int wid = tid >> 5;
    const int wm  = wid & 3;
    const int wn  = wid >> 2;
    const int p0  = blockIdx.x * 128;
    const int b   = p0 / HWP;
    const int ij0 = p0 % HWP;

    const __half* ab = g_agg + (size_t)p0 * CC;
#pragma unroll
    for (int it = 0; it < 8; it++) {
        int idx = tid + it*256;
        int m = idx >> 4, k8 = idx & 15;
        *(uint4*)(As + m*LDH + k8*8) = *(const uint4*)(ab + (size_t)m*CC + k8*8);
    }
#pragma unroll
    for (int it = 0; it < 16; it++) {
        int idx = tid + it*256;
        int k = idx >> 5, n4 = idx & 31;
        *(uint2*)(Bs + k*LDH + n4*4) =
            f4toh4(*(const float4*)(w_proj + k*CC + n4*4));
    }
    if (tid < 128) {
        float bv = b_proj[tid];
#pragma unroll
        for (int r = 0; r < 16; r++) bias_s[r*132 + tid] = bv;
    }
    __syncthreads();

    wmma::fragment<wmma::accumulator, 16,16,16, float> acc[2][4];
#pragma unroll
    for (int mi = 0; mi < 2; mi++)
#pragma unroll
        for (int ni = 0; ni < 4; ni++)
            wmma::load_matrix_sync(acc[mi][ni], bias_s + wn*64 + ni*16,
                                   132, wmma::mem_row_major);

#pragma unroll
    for (int k0 = 0; k0 < CC; k0 += 16) {
        wmma::fragment<wmma::matrix_a, 16,16,16, __half, wmma::row_major> a[2];
#pragma unroll
        for (int mi = 0; mi < 2; mi++)
            wmma::load_matrix_sync(a[mi], As + (wm*32 + mi*16)*LDH + k0, LDH);
        wmma::fragment<wmma::matrix_b, 16,16,16, __half, wmma::row_major> bf[4];
#pragma unroll
        for (int ni = 0; ni < 4; ni++)
            wmma::load_matrix_sync(bf[ni], Bs + k0*LDH + wn*64 + ni*16, LDH);
#pragma unroll
        for (int mi = 0; mi < 2; mi++)
#pragma unroll
            for (int ni = 0; ni < 4; ni++)
                wmma::mma_sync(acc[mi][ni], a[mi], bf[ni], acc[mi][ni]);
    }

    float* ob = out + (size_t)b*CC*HWP + ij0;
#pragma unroll
    for (int mi = 0; mi < 2; mi++)
#pragma unroll
        for (int ni = 0; ni < 4; ni++) {
            int n0 = wn*64 + ni*16;
            int m0 = wm*32 + mi*16;
            wmma::store_matrix_sync(ob + (size_t)n0*HWP + m0, acc[mi][ni],
                                    HWP, wmma::mem_col_major);
        }
}

// ============================================================
extern "C" void kernel_launch(void* const* d_in, const int* in_sizes, int n_in,
                              void* d_out, int out_size)
{
    const float* x      = (const float*)d_in[0];
    const float* sims   = (const float*)d_in[1];
    const float* w_qk   = (const float*)d_in[2];
    const float* b_qk   = (const float*)d_in[3];
    const float* w_v    = (const float*)d_in[4];
    const float* b_v    = (const float*)d_in[5];
    const float* w_proj = (const float*)d_in[6];
    const float* b_proj = (const float*)d_in[7];
    float* out = (float*)d_out;

    cudaFuncSetAttribute(k_qkv_wmma,  cudaFuncAttributeMaxDynamicSharedMemorySize, QKV_SMEM);
    cudaFuncSetAttribute(k_pwd,       cudaFuncAttributeMaxDynamicSharedMemorySize, PWD_SMEM);
    cudaFuncSetAttribute(k_attn,      cudaFuncAttributeMaxDynamicSharedMemorySize, ATT_SMEM);
    cudaFuncSetAttribute(k_proj_wmma, cudaFuncAttributeMaxDynamicSharedMemorySize, PRJ_SMEM);

    k_qkv_wmma <<<dim3(NPIX/128, 3), 256, QKV_SMEM>>>(x, w_qk, b_qk, w_v, b_v);
    k_pwd      <<<dim3(WW/32, HH/8, BB),      dim3(16,8), PWD_SMEM>>>(sims);
    k_attn     <<<dim3(WW/32, HH/8, BB*NHH),  dim3(16,8), ATT_SMEM>>>();
    k_proj_wmma<<<NPIX/128, 256, PRJ_SMEM>>>(w_proj, b_proj, out);
}

// round 14
// speedup vs baseline: 1.0238x; 1.0238x over previous
#include <cuda_runtime.h>
#include <mma.h>
#include <cuda_fp16.h>
#include <math.h>

using namespace nvcuda;

#define BB 8
#define CC 128
#define HH 128
#define WW 128
#define NHH 4
#define HDD 32
#define SG2 256
#define HWP (HH*WW)      // 16384
#define NPIX (BB*HWP)    // 131072
#define KK2 25
#define SCALE 0.17677669529663687f   // 1/sqrt(32)

// ---- scratch (static device arrays; no runtime allocation) ----
static __device__ __align__(16) __half g_q[(size_t)NPIX*CC];
static __device__ __align__(16) __half g_k[(size_t)NPIX*CC];
static __device__ __align__(16) __half g_v[(size_t)NPIX*CC];
static __device__ __align__(16) __half g_agg[(size_t)NPIX*CC];
static __device__ __align__(16) __half g_pwd[(size_t)NPIX*KK2];  // x256 scale (cancels)

#define LDH 136    // fp16 smem row stride for GEMMs (halfs)
#define SLD 40     // fp16 smem row stride for stencils (halfs) — 80 B = 5*16

__device__ __forceinline__ uint2 f4toh4(float4 v) {
    __half2 lo = __floats2half2_rn(v.x, v.y);
    __half2 hi = __floats2half2_rn(v.z, v.w);
    uint2 r;
    r.x = *(unsigned*)&lo;
    r.y = *(unsigned*)&hi;
    return r;
}

__device__ __forceinline__ float dot32v(const __half2* q2,
        uint4 r0, uint4 r1, uint4 r2, uint4 r3)
{
    __half2 a2 = __float2half2_rn(0.f);
    __half2 b2 = __float2half2_rn(0.f);
    a2 = __hfma2(q2[0],  *(__half2*)&r0.x, a2);
    b2 = __hfma2(q2[1],  *(__half2*)&r0.y, b2);
    a2 = __hfma2(q2[2],  *(__half2*)&r0.z, a2);
    b2 = __hfma2(q2[3],  *(__half2*)&r0.w, b2);
    a2 = __hfma2(q2[4],  *(__half2*)&r1.x, a2);
    b2 = __hfma2(q2[5],  *(__half2*)&r1.y, b2);
    a2 = __hfma2(q2[6],  *(__half2*)&r1.z, a2);
    b2 = __hfma2(q2[7],  *(__half2*)&r1.w, b2);
    a2 = __hfma2(q2[8],  *(__half2*)&r2.x, a2);
    b2 = __hfma2(q2[9],  *(__half2*)&r2.y, b2);
    a2 = __hfma2(q2[10], *(__half2*)&r2.z, a2);
    b2 = __hfma2(q2[11], *(__half2*)&r2.w, b2);
    a2 = __hfma2(q2[12], *(__half2*)&r3.x, a2);
    b2 = __hfma2(q2[13], *(__half2*)&r3.y, b2);
    a2 = __hfma2(q2[14], *(__half2*)&r3.z, a2);
    b2 = __hfma2(q2[15], *(__half2*)&r3.w, b2);
    float2 fa = __half22float2(a2);
    float2 fb = __half22float2(b2);
    return (fa.x + fa.y) + (fb.x + fb.y);
}

__device__ __forceinline__ void fma16(__half2* o, __half2 wk2, uint4 r0, uint4 r1)
{
    o[0] = __hfma2(wk2, *(__half2*)&r0.x, o[0]);
    o[1] = __hfma2(wk2, *(__half2*)&r0.y, o[1]);
    o[2] = __hfma2(wk2, *(__half2*)&r0.z, o[2]);
    o[3] = __hfma2(wk2, *(__half2*)&r0.w, o[3]);
    o[4] = __hfma2(wk2, *(__half2*)&r1.x, o[4]);
    o[5] = __hfma2(wk2, *(__half2*)&r1.y, o[5]);
    o[6] = __hfma2(wk2, *(__half2*)&r1.z, o[6]);
    o[7] = __hfma2(wk2, *(__half2*)&r1.w, o[7]);
}

// ============================================================
// Kernel 1: QKV GEMM via WMMA fp16 (fp32 acc). (R12-proven: A staged
// once, 3 sequential N-passes.)
// ============================================================
#define QKV_SMEM (16*132*4 + 2*128*LDH*2)   // 78080 B -> 2 blocks/SM

__global__ void __launch_bounds__(256, 2)
k_qkv_wmma(const float* __restrict__ x, const float* __restrict__ w_qk,
           const float* __restrict__ b_qk, const float* __restrict__ w_v,
           const float* __restrict__ b_v)
{
    extern __shared__ char smraw[];
    float*  bias_s = (float*)smraw;                    // [16][132]
    __half* As     = (__half*)(smraw + 16*132*4);      // [k=128][m=128] ld LDH
    __half* Bs     = As + 128*LDH;                     // [k=128][n=128] ld LDH

    const int tid = threadIdx.x;
    const int wid = tid >> 5;
    const int wm  = wid & 3;
    const int wn  = wid >> 2;
    const int p0  = blockIdx.x * 128;
    const int b   = p0 / HWP;
    const int ij0 = p0 % HWP;
    const float* xb = x + (size_t)b*CC*HWP + ij0;

#pragma unroll
    for (int it = 0; it < 16; it++) {
        int idx = tid + it*256;
        int k = idx >> 5, m4 = idx & 31;
        *(uint2*)(As + k*LDH + m4*4) =
            f4toh4(*(const float4*)(xb + (size_t)k*HWP + m4*4));
    }

    for (int nt = 0; nt < 3; nt++) {
        __syncthreads();
#pragma unroll
        for (int it = 0; it < 16; it++) {
            int idx = tid + it*256;
            int k = idx >> 5, n4 = idx & 31;
            const float* src = (nt < 2) ? (w_qk + k*2*CC + nt*128 + n4*4)
                                        : (w_v  + k*CC  + n4*4);
            *(uint2*)(Bs + k*LDH + n4*4) = f4toh4(*(const float4*)src);
        }
        if (tid < 128) {
            float bv = (nt < 2) ? b_qk[nt*128 + tid] : b_v[tid];
#pragma unroll
            for (int r = 0; r < 16; r++) bias_s[r*132 + tid] = bv;
        }
        __syncthreads();

        wmma::fragment<wmma::accumulator, 16,16,16, float> acc[2][4];
#pragma unroll
        for (int mi = 0; mi < 2; mi++)
#pragma unroll
            for (int ni = 0; ni < 4; ni++)
                wmma::load_matrix_sync(acc[mi][ni], bias_s + wn*64 + ni*16,
                                       132, wmma::mem_row_major);

#pragma unroll
        for (int k0 = 0; k0 < CC; k0 += 16) {
            wmma::fragment<wmma::matrix_a, 16,16,16, __half, wmma::col_major> a[2];
#pragma unroll
            for (int mi = 0; mi < 2; mi++)
                wmma::load_matrix_sync(a[mi], As + k0*LDH + wm*32 + mi*16, LDH);
            wmma::fragment<wmma::matrix_b, 16,16,16, __half, wmma::row_major> bf[4];
#pragma unroll
            for (int ni = 0; ni < 4; ni++)
                wmma::load_matrix_sync(bf[ni], Bs + k0*LDH + wn*64 + ni*16, LDH);
#pragma unroll
            for (int mi = 0; mi < 2; mi++)
#pragma unroll
                for (int ni = 0; ni < 4; ni++)
                    wmma::mma_sync(acc[mi][ni], a[mi], bf[ni], acc[mi][ni]);
        }

        __half* dstbase = (nt == 0) ? g_q : (nt == 1) ? g_k : g_v;
#pragma unroll
        for (int mi = 0; mi < 2; mi++)
#pragma unroll
            for (int ni = 0; ni < 4; ni++) {
                wmma::fragment<wmma::accumulator, 16,16,16, __half> hacc;
#pragma unroll
                for (int e = 0; e < 8; e++)
                    hacc.x[e] = __float2half(acc[mi][ni].x[e]);
                int n0 = wn*64 + ni*16;
                int head = n0 >> 5, d0 = n0 & 31;
                __half* dst = dstbase +
                    ((size_t)(b*NHH + head)*HWP + ij0 + wm*32 + mi*16)*HDD + d0;
                wmma::store_matrix_sync(dst, hacc, HDD, wmma::mem_row_major);
            }
    }
}

// ============================================================
// Kernel 2: pwd, pixel-paired + XOR rotation, 16x32 tile
// (halo amplification 1.41x vs 1.69x), 256 threads, 2 blocks/SM.
// ============================================================
#define PWD_SMEM (720*SLD*2)   // 57600 B

__global__ void __launch_bounds__(256, 2)
k_pwd(const float* __restrict__ sims)
{
    extern __shared__ __half Sh[];  // [720][40]
    const int b  = blockIdx.z;
    const int i0 = blockIdx.y * 16;
    const int j0 = blockIdx.x * 32;
    const int tx = threadIdx.x;     // 0..15 -> pixel pair (2tx, 2tx+1)
    const int ty = threadIdx.y;     // 0..15
    const int tid = ty*16 + tx;
    const int rot = (tx >> 2) & 1;
    const float* sb = sims + (size_t)b*HWP*SG2;

    float acc0[KK2], acc1[KK2];
#pragma unroll
    for (int k=0;k<KK2;k++) { acc0[k]=0.f; acc1[k]=0.f; }

    for (int scc = 0; scc < SG2; scc += 32) {
        __syncthreads();
        for (int idx = tid; idx < 720*4; idx += 256) {
            int pix = idx >> 2, v = idx & 3;
            int hr = pix / 36, hc = pix - hr*36;
            int gi = i0 - 2 + hr, gj = j0 - 2 + hc;
            uint4 o = make_uint4(0,0,0,0);
            if ((unsigned)gi < HH && (unsigned)gj < WW) {
                const float* src = sb + ((size_t)gi*WW + gj)*SG2 + scc + v*8;
                float4 f0 = *(const float4*)src;
                float4 f1 = *(const float4*)(src + 4);
                f0.x*=16.f; f0.y*=16.f; f0.z*=16.f; f0.w*=16.f;
                f1.x*=16.f; f1.y*=16.f; f1.z*=16.f; f1.w*=16.f;
                uint2 h0 = f4toh4(f0), h1 = f4toh4(f1);
                o = make_uint4(h0.x, h0.y, h1.x, h1.y);
            }
            *(uint4*)(Sh + pix*SLD + v*8) = o;
        }
        __syncthreads();

        __half2 oa[16], ob[16];
        {
            const __half* p0 = Sh + ((ty+2)*36 + (2*tx+2))*SLD;
#pragma unroll
            for (int v=0; v<4; v++) {
                uint4 r = *(const uint4*)(p0 + ((v^rot)<<3));
                oa[v*4+0]=*(__half2*)&r.x; oa[v*4+1]=*(__half2*)&r.y;
                oa[v*4+2]=*(__half2*)&r.z; oa[v*4+3]=*(__half2*)&r.w;
                uint4 s = *(const uint4*)(p0 + SLD + ((v^rot)<<3));
                ob[v*4+0]=*(__half2*)&s.x; ob[v*4+1]=*(__half2*)&s.y;
                ob[v*4+2]=*(__half2*)&s.z; ob[v*4+3]=*(__half2*)&s.w;
            }
        }
#pragma unroll
        for (int di=0; di<5; di++) {
#pragma unroll
            for (int djc=0; djc<6; djc++) {
                const __half* np = Sh + ((ty+di)*36 + (2*tx+djc))*SLD;
                uint4 r0 = *(const uint4*)(np + ((0^rot)<<3));
                uint4 r1 = *(const uint4*)(np + ((1^rot)<<3));
                uint4 r2 = *(const uint4*)(np + ((2^rot)<<3));
                uint4 r3 = *(const uint4*)(np + ((3^rot)<<3));
                if (djc < 5) acc0[di*5+djc]   += dot32v(oa, r0,r1,r2,r3);
                if (djc > 0) acc1[di*5+djc-1] += dot32v(ob, r0,r1,r2,r3);
            }
        }
    }
    const size_t p = (size_t)b*HWP + (size_t)(i0+ty)*WW + (j0+2*tx);
#pragma unroll
    for (int k=0;k<KK2;k++) {
        g_pwd[p*KK2 + k]     = __float2half(acc0[k]);
        g_pwd[(p+1)*KK2 + k] = __float2half(acc1[k]);
    }
}

// ============================================================
// Kernel 3: attention + V agg — R12-proven: single K->V buffer,
// pixel-paired + XOR rotation, weights packed half2 early.
// ============================================================
#define ATT_SMEM (432*SLD*2)   // 34560 B

__global__ void __launch_bounds__(128, 4)
k_attn()
{
    extern __shared__ __half Hs[];  // [432][40]: K then V
    const int bh = blockIdx.z;
    const int b  = bh >> 2;
    const int h  = bh & 3;
    const int i0 = blockIdx.y * 8;
    const int j0 = blockIdx.x * 32;
    const int tx = threadIdx.x;     // 0..15
    const int ty = threadIdx.y;     // 0..7
    const int tid = ty*16 + tx;
    const int rot = (tx >> 2) & 1;
    const size_t headoff = (size_t)bh*HWP*HDD;
    const int ij0 = (i0+ty)*WW + (j0 + 2*tx);

    // ---- stage K ----
    const __half* kb = g_k + headoff;
    for (int idx = tid; idx < 432*4; idx += 128) {
        int pix = idx >> 2, v = idx & 3;
        int hr = pix / 36, hc = pix - hr*36;
        int gi = i0 - 2 + hr, gj = j0 - 2 + hc;
        uint4 kp = make_uint4(0,0,0,0);
        if ((unsigned)gi < HH && (unsigned)gj < WW)
            kp = *(const uint4*)(kb + (size_t)(gi*WW + gj)*HDD + v*8);
        *(uint4*)(Hs + pix*SLD + v*8) = kp;
    }

    // q pair, loaded from global in permuted chunk order
    __half2 qa[16], qb[16];
    {
        const __half* qp = g_q + headoff + (size_t)ij0*HDD;
#pragma unroll
        for (int v=0; v<4; v++) {
            uint4 r = *(const uint4*)(qp + ((v^rot)<<3));
            qa[v*4+0]=*(__half2*)&r.x; qa[v*4+1]=*(__half2*)&r.y;
            qa[v*4+2]=*(__half2*)&r.z; qa[v*4+3]=*(__half2*)&r.w;
            uint4 s = *(const uint4*)(qp + HDD + ((v^rot)<<3));
            qb[v*4+0]=*(__half2*)&s.x; qb[v*4+1]=*(__half2*)&s.y;
            qb[v*4+2]=*(__half2*)&s.z; qb[v*4+3]=*(__half2*)&s.w;
        }
    }
    __syncthreads();

    // ---- scores for the pair; weights packed half2 immediately ----
    const __half* pwp = g_pwd + ((size_t)b*HWP + ij0)*KK2;
    __half2 wh2[KK2];
    float ssum0 = 0.f, ssum1 = 0.f;
#pragma unroll
    for (int di=0; di<5; di++) {
#pragma unroll
        for (int djc=0; djc<6; djc++) {
            const __half* np = Hs + ((ty+di)*36 + (2*tx+djc))*SLD;
            uint4 r0 = *(const uint4*)(np + ((0^rot)<<3));
            uint4 r1 = *(const uint4*)(np + ((1^rot)<<3));
            uint4 r2 = *(const uint4*)(np + ((2^rot)<<3));
            uint4 r3 = *(const uint4*)(np + ((3^rot)<<3));
            if (djc < 5) {
                int kk = di*5+djc;
                float s = dot32v(qa, r0,r1,r2,r3);
                float w0 = __expf(s * SCALE) * __half2float(pwp[kk]);
                ssum0 += w0;
                wh2[kk] = __halves2half2(__float2half(w0), __float2half(0.f));
            }
            if (djc > 0) {
                int kk = di*5+djc-1;
                float s = dot32v(qb, r0,r1,r2,r3);
                float w1 = __expf(s * SCALE) * __half2float(pwp[KK2+kk]);
                ssum1 += w1;
                wh2[kk] = __halves2half2(__low2half(wh2[kk]), __float2half(w1));
            }
        }
    }
    {
        __half2 inv2 = __floats2half2_rn(1.f / fmaxf(ssum0, 1e-30f),
                                         1.f / fmaxf(ssum1, 1e-30f));
#pragma unroll
        for (int k=0;k<KK2;k++) wh2[k] = __hmul2(wh2[k], inv2);
    }

    __syncthreads();   // done reading K

    // ---- stage V (reuse buffer) ----
    const __half* vb = g_v + headoff;
    for (int idx = tid; idx < 432*4; idx += 128) {
        int pix = idx >> 2, v = idx & 3;
        int hr = pix / 36, hc = pix - hr*36;
        int gi = i0 - 2 + hr, gj = j0 - 2 + hc;
        uint4 vp = make_uint4(0,0,0,0);
        if ((unsigned)gi < HH && (unsigned)gj < WW)
            vp = *(const uint4*)(vb + (size_t)(gi*WW + gj)*HDD + v*8);
        *(uint4*)(Hs + pix*SLD + v*8) = vp;
    }
    __syncthreads();

    // ---- V aggregation: two channel-halves, chunk-rotated loads ----
    __half* ag = g_agg + ((size_t)b*HWP + ij0)*CC + h*HDD;
#pragma unroll
    for (int ch = 0; ch < 2; ch++) {
        float out0[16], out1[16];
#pragma unroll
        for (int j=0;j<16;j++) { out0[j]=0.f; out1[j]=0.f; }
#pragma unroll
        for (int di=0; di<5; di++) {
            __half2 oa[8], ob[8];
#pragma unroll
            for (int j=0;j<8;j++) { oa[j]=__float2half2_rn(0.f); ob[j]=__float2half2_rn(0.f); }
#pragma unroll
            for (int djc=0; djc<6; djc++) {
                const __half* np = Hs + ((ty+di)*36 + (2*tx+djc))*SLD + ch*16;
                uint4 r0 = *(const uint4*)(np + ((0^rot)<<3));
                uint4 r1 = *(const uint4*)(np + ((1^rot)<<3));
                if (djc < 5) fma16(oa, __low2half2 (wh2[di*5+djc]),   r0, r1);
                if (djc > 0) fma16(ob, __high2half2(wh2[di*5+djc-1]), r0, r1);
            }
#pragma unroll
            for (int j=0;j<8;j++) {
                float2 fa = __half22float2(oa[j]);
                float2 fb = __half22float2(ob[j]);
                out0[2*j] += fa.x; out0[2*j+1] += fa.y;
                out1[2*j] += fb.x; out1[2*j+1] += fb.y;
            }
        }
#pragma unroll
        for (int v=0; v<2; v++) {
            uint2 h0 = f4toh4(make_float4(out0[v*8+0],out0[v*8+1],out0[v*8+2],out0[v*8+3]));
            uint2 h1 = f4toh4(make_float4(out0[v*8+4],out0[v*8+5],out0[v*8+6],out0[v*8+7]));
            *(uint4*)(ag + ch*16 + ((v^rot)<<3)) = make_uint4(h0.x,h0.y,h1.x,h1.y);
            uint2 g0 = f4toh4(make_float4(out1[v*8+0],out1[v*8+1],out1[v*8+2],out1[v*8+3]));
            uint2 g1 = f4toh4(make_float4(out1[v*8+4],out1[v*8+5],out1[v*8+6],out1[v*8+7]));
            *(uint4*)(ag + CC + ch*16 + ((v^rot)<<3)) = make_uint4(g0.x,g0.y,g1.x,g1.y);
        }
    }
}

// ============================================================
// Kernel 4: proj GEMM via WMMA fp16 + free BCHW transpose store.
// (R10-proven, unchanged.)
// ============================================================
#define PRJ_SMEM (16*132*4 + 2*128*LDH*2)   // 78080 B -> 2 blocks/SM

__global__ void __launch_bounds__(256, 2)
k_proj_wmma(const float* __restrict__ w_proj, const float* __restrict__ b_proj,
            float* __restrict__ out)
{
    extern __shared__ char smraw[];
    float*  bias_s = (float*)smraw;                    // [16][132]
    __half* As     = (__half*)(smraw + 16*132*4);      // [m=128][k=128] ld LDH
    __half* Bs     = As + 128*LDH;                     // [k=128][n=128] ld LDH

    const int tid = threadIdx.x;
    const int wid = tid >> 5;
    const int wm  = wid & 3;
    const int wn  = wid >> 2;
    const int p0  = blockIdx.x * 128;
    const int b   = p0 / HWP;
    const int ij0 = p0 % HWP;

    const __half* ab = g_agg + (size_t)p0 * CC;
#pragma unroll
    for (int it = 0; it < 8; it++) {
        int idx = tid + it*256;
        int m = idx >> 4, k8 = idx & 15;
        *(uint4*)(As + m*LDH + k8*8) = *(const uint4*)(ab + (size_t)m*CC + k8*8);
    }
#pragma unroll
    for (int it = 0; it < 16; it++) {
        int idx = tid + it*256;
        int k = idx >> 5, n4 = idx & 31;
        *(uint2*)(Bs + k*LDH + n4*4) =
            f4toh4(*(const float4*)(w_proj + k*CC + n4*4));
    }
    if (tid < 128) {
        float bv = b_proj[tid];
#pragma unroll
        for (int r = 0; r < 16; r++) bias_s[r*132 + tid] = bv;
    }
    __syncthreads();

    wmma::fragment<wmma::accumulator, 16,16,16, float> acc[2][4];
#pragma unroll
    for (int mi = 0; mi < 2; mi++)
#pragma unroll
        for (int ni = 0; ni < 4; ni++)
            wmma::load_matrix_sync(acc[mi][ni], bias_s + wn*64 + ni*16,
                                   132, wmma::mem_row_major);

#pragma unroll
    for (int k0 = 0; k0 < CC; k0 += 16) {
        wmma::fragment<wmma::matrix_a, 16,16,16, __half, wmma::row_major> a[2];
#pragma unroll
        for (int mi = 0; mi < 2; mi++)
            wmma::load_matrix_sync(a[mi], As + (wm*32 + mi*16)*LDH + k0, LDH);
        wmma::fragment<wmma::matrix_b, 16,16,16, __half, wmma::row_major> bf[4];
#pragma unroll
        for (int ni = 0; ni < 4; ni++)
            wmma::load_matrix_sync(bf[ni], Bs + k0*LDH + wn*64 + ni*16, LDH);
#pragma unroll
        for (int mi = 0; mi < 2; mi++)
#pragma unroll
            for (int ni = 0; ni < 4; ni++)
                wmma::mma_sync(acc[mi][ni], a[mi], bf[ni], acc[mi][ni]);
    }

    float* ob = out + (size_t)b*CC*HWP + ij0;
#pragma unroll
    for (int mi = 0; mi < 2; mi++)
#pragma unroll
        for (int ni = 0; ni < 4; ni++) {
            int n0 = wn*64 + ni*16;
            int m0 = wm*32 + mi*16;
            wmma::store_matrix_sync(ob + (size_t)n0*HWP + m0, acc[mi][ni],
                                    HWP, wmma::mem_col_major);
        }
}

// ============================================================
extern "C" void kernel_launch(void* const* d_in, const int* in_sizes, int n_in,
                              void* d_out, int out_size)
{
    const float* x      = (const float*)d_in[0];
    const float* sims   = (const float*)d_in[1];
    const float* w_qk   = (const float*)d_in[2];
    const float* b_qk   = (const float*)d_in[3];
    const float* w_v    = (const float*)d_in[4];
    const float* b_v    = (const float*)d_in[5];
    const float* w_proj = (const float*)d_in[6];
    const float* b_proj = (const float*)d_in[7];
    float* out = (float*)d_out;

    cudaFuncSetAttribute(k_qkv_wmma,  cudaFuncAttributeMaxDynamicSharedMemorySize, QKV_SMEM);
    cudaFuncSetAttribute(k_pwd,       cudaFuncAttributeMaxDynamicSharedMemorySize, PWD_SMEM);
    cudaFuncSetAttribute(k_attn,      cudaFuncAttributeMaxDynamicSharedMemorySize, ATT_SMEM);
    cudaFuncSetAttribute(k_proj_wmma, cudaFuncAttributeMaxDynamicSharedMemorySize, PRJ_SMEM);

    k_qkv_wmma <<<NPIX/128, 256, QKV_SMEM>>>(x, w_qk, b_qk, w_v, b_v);
    k_pwd      <<<dim3(WW/32, HH/16, BB),     dim3(16,16), PWD_SMEM>>>(sims);
    k_attn     <<<dim3(WW/32, HH/8, BB*NHH),  dim3(16,8),  ATT_SMEM>>>();
    k_proj_wmma<<<NPIX/128, 256, PRJ_SMEM>>>(w_proj, b_proj, out);
}

// round 15
// speedup vs baseline: 1.1182x; 1.0923x over previous
#include <cuda_runtime.h>
#include <cuda_pipeline.h>
#include <mma.h>
#include <cuda_fp16.h>
#include <math.h>

using namespace nvcuda;

#define BB 8
#define CC 128
#define HH 128
#define WW 128
#define NHH 4
#define HDD 32
#define SG2 256
#define HWP (HH*WW)      // 16384
#define NPIX (BB*HWP)    // 131072
#define KK2 25
#define SCALE 0.17677669529663687f   // 1/sqrt(32)

// ---- scratch (static device arrays; no runtime allocation) ----
static __device__ __align__(16) __half g_q[(size_t)NPIX*CC];
static __device__ __align__(16) __half g_k[(size_t)NPIX*CC];
static __device__ __align__(16) __half g_v[(size_t)NPIX*CC];
static __device__ __align__(16) __half g_agg[(size_t)NPIX*CC];
static __device__ __align__(16) __half g_pwd[(size_t)NPIX*KK2];  // x256 scale (cancels)

#define LDH 136    // fp16 smem row stride for GEMMs (halfs)
#define SLD 40     // fp16 smem row stride for stencils (halfs) — 80 B = 5*16

__device__ __forceinline__ uint2 f4toh4(float4 v) {
    __half2 lo = __floats2half2_rn(v.x, v.y);
    __half2 hi = __floats2half2_rn(v.z, v.w);
    uint2 r;
    r.x = *(unsigned*)&lo;
    r.y = *(unsigned*)&hi;
    return r;
}

__device__ __forceinline__ float dot32v(const __half2* q2,
        uint4 r0, uint4 r1, uint4 r2, uint4 r3)
{
    __half2 a2 = __float2half2_rn(0.f);
    __half2 b2 = __float2half2_rn(0.f);
    a2 = __hfma2(q2[0],  *(__half2*)&r0.x, a2);
    b2 = __hfma2(q2[1],  *(__half2*)&r0.y, b2);
    a2 = __hfma2(q2[2],  *(__half2*)&r0.z, a2);
    b2 = __hfma2(q2[3],  *(__half2*)&r0.w, b2);
    a2 = __hfma2(q2[4],  *(__half2*)&r1.x, a2);
    b2 = __hfma2(q2[5],  *(__half2*)&r1.y, b2);
    a2 = __hfma2(q2[6],  *(__half2*)&r1.z, a2);
    b2 = __hfma2(q2[7],  *(__half2*)&r1.w, b2);
    a2 = __hfma2(q2[8],  *(__half2*)&r2.x, a2);
    b2 = __hfma2(q2[9],  *(__half2*)&r2.y, b2);
    a2 = __hfma2(q2[10], *(__half2*)&r2.z, a2);
    b2 = __hfma2(q2[11], *(__half2*)&r2.w, b2);
    a2 = __hfma2(q2[12], *(__half2*)&r3.x, a2);
    b2 = __hfma2(q2[13], *(__half2*)&r3.y, b2);
    a2 = __hfma2(q2[14], *(__half2*)&r3.z, a2);
    b2 = __hfma2(q2[15], *(__half2*)&r3.w, b2);
    float2 fa = __half22float2(a2);
    float2 fb = __half22float2(b2);
    return (fa.x + fa.y) + (fb.x + fb.y);
}

__device__ __forceinline__ void fma16(__half2* o, __half2 wk2, uint4 r0, uint4 r1)
{
    o[0] = __hfma2(wk2, *(__half2*)&r0.x, o[0]);
    o[1] = __hfma2(wk2, *(__half2*)&r0.y, o[1]);
    o[2] = __hfma2(wk2, *(__half2*)&r0.z, o[2]);
    o[3] = __hfma2(wk2, *(__half2*)&r0.w, o[3]);
    o[4] = __hfma2(wk2, *(__half2*)&r1.x, o[4]);
    o[5] = __hfma2(wk2, *(__half2*)&r1.y, o[5]);
    o[6] = __hfma2(wk2, *(__half2*)&r1.z, o[6]);
    o[7] = __hfma2(wk2, *(__half2*)&r1.w, o[7]);
}

// ============================================================
// Kernel 1: QKV GEMM via WMMA fp16 (fp32 acc). (R12-proven.)
// ============================================================
#define QKV_SMEM (16*132*4 + 2*128*LDH*2)   // 78080 B -> 2 blocks/SM

__global__ void __launch_bounds__(256, 2)
k_qkv_wmma(const float* __restrict__ x, const float* __restrict__ w_qk,
           const float* __restrict__ b_qk, const float* __restrict__ w_v,
           const float* __restrict__ b_v)
{
    extern __shared__ char smraw[];
    float*  bias_s = (float*)smraw;                    // [16][132]
    __half* As     = (__half*)(smraw + 16*132*4);      // [k=128][m=128] ld LDH
    __half* Bs     = As + 128*LDH;                     // [k=128][n=128] ld LDH

    const int tid = threadIdx.x;
    const int wid = tid >> 5;
    const int wm  = wid & 3;
    const int wn  = wid >> 2;
    const int p0  = blockIdx.x * 128;
    const int b   = p0 / HWP;
    const int ij0 = p0 % HWP;
    const float* xb = x + (size_t)b*CC*HWP + ij0;

#pragma unroll
    for (int it = 0; it < 16; it++) {
        int idx = tid + it*256;
        int k = idx >> 5, m4 = idx & 31;
        *(uint2*)(As + k*LDH + m4*4) =
            f4toh4(*(const float4*)(xb + (size_t)k*HWP + m4*4));
    }

    for (int nt = 0; nt < 3; nt++) {
        __syncthreads();
#pragma unroll
        for (int it = 0; it < 16; it++) {
            int idx = tid + it*256;
            int k = idx >> 5, n4 = idx & 31;
            const float* src = (nt < 2) ? (w_qk + k*2*CC + nt*128 + n4*4)
                                        : (w_v  + k*CC  + n4*4);
            *(uint2*)(Bs + k*LDH + n4*4) = f4toh4(*(const float4*)src);
        }
        if (tid < 128) {
            float bv = (nt < 2) ? b_qk[nt*128 + tid] : b_v[tid];
#pragma unroll
            for (int r = 0; r < 16; r++) bias_s[r*132 + tid] = bv;
        }
        __syncthreads();

        wmma::fragment<wmma::accumulator, 16,16,16, float> acc[2][4];
#pragma unroll
        for (int mi = 0; mi < 2; mi++)
#pragma unroll
            for (int ni = 0; ni < 4; ni++)
                wmma::load_matrix_sync(acc[mi][ni], bias_s + wn*64 + ni*16,
                                       132, wmma::mem_row_major);

#pragma unroll
        for (int k0 = 0; k0 < CC; k0 += 16) {
            wmma::fragment<wmma::matrix_a, 16,16,16, __half, wmma::col_major> a[2];
#pragma unroll
            for (int mi = 0; mi < 2; mi++)
                wmma::load_matrix_sync(a[mi], As + k0*LDH + wm*32 + mi*16, LDH);
            wmma::fragment<wmma::matrix_b, 16,16,16, __half, wmma::row_major> bf[4];
#pragma unroll
            for (int ni = 0; ni < 4; ni++)
                wmma::load_matrix_sync(bf[ni], Bs + k0*LDH + wn*64 + ni*16, LDH);
#pragma unroll
            for (int mi = 0; mi < 2; mi++)
#pragma unroll
                for (int ni = 0; ni < 4; ni++)
                    wmma::mma_sync(acc[mi][ni], a[mi], bf[ni], acc[mi][ni]);
        }

        __half* dstbase = (nt == 0) ? g_q : (nt == 1) ? g_k : g_v;
#pragma unroll
        for (int mi = 0; mi < 2; mi++)
#pragma unroll
            for (int ni = 0; ni < 4; ni++) {
                wmma::fragment<wmma::accumulator, 16,16,16, __half> hacc;
#pragma unroll
                for (int e = 0; e < 8; e++)
                    hacc.x[e] = __float2half(acc[mi][ni].x[e]);
                int n0 = wn*64 + ni*16;
                int head = n0 >> 5, d0 = n0 & 31;
                __half* dst = dstbase +
                    ((size_t)(b*NHH + head)*HWP + ij0 + wm*32 + mi*16)*HDD + d0;
                wmma::store_matrix_sync(dst, hacc, HDD, wmma::mem_row_major);
            }
    }
}

// ============================================================
// Kernel 2: pwd, pixel-paired + XOR chunk rotation. (R12-proven.)
// ============================================================
#define PWD_SMEM (432*SLD*2)   // 34560 B

__global__ void __launch_bounds__(128, 4)
k_pwd(const float* __restrict__ sims)
{
    extern __shared__ __half Sh[];  // [432][40]
    const int b  = blockIdx.z;
    const int i0 = blockIdx.y * 8;
    const int j0 = blockIdx.x * 32;
    const int tx = threadIdx.x;     // 0..15
    const int ty = threadIdx.y;     // 0..7
    const int tid = ty*16 + tx;
    const int rot = (tx >> 2) & 1;
    const float* sb = sims + (size_t)b*HWP*SG2;

    float acc0[KK2], acc1[KK2];
#pragma unroll
    for (int k=0;k<KK2;k++) { acc0[k]=0.f; acc1[k]=0.f; }

    for (int scc = 0; scc < SG2; scc += 32) {
        __syncthreads();
        for (int idx = tid; idx < 432*4; idx += 128) {
            int pix = idx >> 2, v = idx & 3;
            int hr = pix / 36, hc = pix - hr*36;
            int gi = i0 - 2 + hr, gj = j0 - 2 + hc;
            uint4 o = make_uint4(0,0,0,0);
            if ((unsigned)gi < HH && (unsigned)gj < WW) {
                const float* src = sb + ((size_t)gi*WW + gj)*SG2 + scc + v*8;
                float4 f0 = *(const float4*)src;
                float4 f1 = *(const float4*)(src + 4);
                f0.x*=16.f; f0.y*=16.f; f0.z*=16.f; f0.w*=16.f;
                f1.x*=16.f; f1.y*=16.f; f1.z*=16.f; f1.w*=16.f;
                uint2 h0 = f4toh4(f0), h1 = f4toh4(f1);
                o = make_uint4(h0.x, h0.y, h1.x, h1.y);
            }
            *(uint4*)(Sh + pix*SLD + v*8) = o;
        }
        __syncthreads();

        __half2 oa[16], ob[16];
        {
            const __half* p0 = Sh + ((ty+2)*36 + (2*tx+2))*SLD;
#pragma unroll
            for (int v=0; v<4; v++) {
                uint4 r = *(const uint4*)(p0 + ((v^rot)<<3));
                oa[v*4+0]=*(__half2*)&r.x; oa[v*4+1]=*(__half2*)&r.y;
                oa[v*4+2]=*(__half2*)&r.z; oa[v*4+3]=*(__half2*)&r.w;
                uint4 s = *(const uint4*)(p0 + SLD + ((v^rot)<<3));
                ob[v*4+0]=*(__half2*)&s.x; ob[v*4+1]=*(__half2*)&s.y;
                ob[v*4+2]=*(__half2*)&s.z; ob[v*4+3]=*(__half2*)&s.w;
            }
        }
#pragma unroll
        for (int di=0; di<5; di++) {
#pragma unroll
            for (int djc=0; djc<6; djc++) {
                const __half* np = Sh + ((ty+di)*36 + (2*tx+djc))*SLD;
                uint4 r0 = *(const uint4*)(np + ((0^rot)<<3));
                uint4 r1 = *(const uint4*)(np + ((1^rot)<<3));
                uint4 r2 = *(const uint4*)(np + ((2^rot)<<3));
                uint4 r3 = *(const uint4*)(np + ((3^rot)<<3));
                if (djc < 5) acc0[di*5+djc]   += dot32v(oa, r0,r1,r2,r3);
                if (djc > 0) acc1[di*5+djc-1] += dot32v(ob, r0,r1,r2,r3);
            }
        }
    }
    const size_t p = (size_t)b*HWP + (size_t)(i0+ty)*WW + (j0+2*tx);
#pragma unroll
    for (int k=0;k<KK2;k++) {
        g_pwd[p*KK2 + k]     = __float2half(acc0[k]);
        g_pwd[(p+1)*KK2 + k] = __float2half(acc1[k]);
    }
}

// ============================================================
// Kernel 3: attention + V agg — R12 structure, staging via cp.async
// (LDGSTS, zfill for OOB). Single K->V buffer, 4 blocks/SM.
// ============================================================
#define ATT_SMEM (432*SLD*2)   // 34560 B

__global__ void __launch_bounds__(128, 4)
k_attn()
{
    extern __shared__ __half Hs[];  // [432][40]: K then V
    const int bh = blockIdx.z;
    const int b  = bh >> 2;
    const int h  = bh & 3;
    const int i0 = blockIdx.y * 8;
    const int j0 = blockIdx.x * 32;
    const int tx = threadIdx.x;     // 0..15
    const int ty = threadIdx.y;     // 0..7
    const int tid = ty*16 + tx;
    const int rot = (tx >> 2) & 1;
    const size_t headoff = (size_t)bh*HWP*HDD;
    const int ij0 = (i0+ty)*WW + (j0 + 2*tx);

    // ---- stage K via cp.async ----
    const __half* kb = g_k + headoff;
    for (int idx = tid; idx < 432*4; idx += 128) {
        int pix = idx >> 2, v = idx & 3;
        int hr = pix / 36, hc = pix - hr*36;
        int gi = i0 - 2 + hr, gj = j0 - 2 + hc;
        bool ok = ((unsigned)gi < HH) && ((unsigned)gj < WW);
        int cgi = ok ? gi : 0, cgj = ok ? gj : 0;
        __pipeline_memcpy_async(Hs + pix*SLD + v*8,
            kb + (size_t)(cgi*WW + cgj)*HDD + v*8, 16, ok ? 0 : 16);
    }
    __pipeline_commit();

    // q pair, loaded from global in permuted chunk order (overlaps K copy)
    __half2 qa[16], qb[16];
    {
        const __half* qp = g_q + headoff + (size_t)ij0*HDD;
#pragma unroll
        for (int v=0; v<4; v++) {
            uint4 r = *(const uint4*)(qp + ((v^rot)<<3));
            qa[v*4+0]=*(__half2*)&r.x; qa[v*4+1]=*(__half2*)&r.y;
            qa[v*4+2]=*(__half2*)&r.z; qa[v*4+3]=*(__half2*)&r.w;
            uint4 s = *(const uint4*)(qp + HDD + ((v^rot)<<3));
            qb[v*4+0]=*(__half2*)&s.x; qb[v*4+1]=*(__half2*)&s.y;
            qb[v*4+2]=*(__half2*)&s.z; qb[v*4+3]=*(__half2*)&s.w;
        }
    }
    __pipeline_wait_prior(0);
    __syncthreads();

    // ---- scores for the pair; weights packed half2 immediately ----
    const __half* pwp = g_pwd + ((size_t)b*HWP + ij0)*KK2;
    __half2 wh2[KK2];
    float ssum0 = 0.f, ssum1 = 0.f;
#pragma unroll
    for (int di=0; di<5; di++) {
#pragma unroll
        for (int djc=0; djc<6; djc++) {
            const __half* np = Hs + ((ty+di)*36 + (2*tx+djc))*SLD;
            uint4 r0 = *(const uint4*)(np + ((0^rot)<<3));
            uint4 r1 = *(const uint4*)(np + ((1^rot)<<3));
            uint4 r2 = *(const uint4*)(np + ((2^rot)<<3));
            uint4 r3 = *(const uint4*)(np + ((3^rot)<<3));
            if (djc < 5) {
                int kk = di*5+djc;
                float s = dot32v(qa, r0,r1,r2,r3);
                float w0 = __expf(s * SCALE) * __half2float(pwp[kk]);
                ssum0 += w0;
                wh2[kk] = __halves2half2(__float2half(w0), __float2half(0.f));
            }
            if (djc > 0) {
                int kk = di*5+djc-1;
                float s = dot32v(qb, r0,r1,r2,r3);
                float w1 = __expf(s * SCALE) * __half2float(pwp[KK2+kk]);
                ssum1 += w1;
                wh2[kk] = __halves2half2(__low2half(wh2[kk]), __float2half(w1));
            }
        }
    }
    {
        __half2 inv2 = __floats2half2_rn(1.f / fmaxf(ssum0, 1e-30f),
                                         1.f / fmaxf(ssum1, 1e-30f));
#pragma unroll
        for (int k=0;k<KK2;k++) wh2[k] = __hmul2(wh2[k], inv2);
    }

    __syncthreads();   // done reading K

    // ---- stage V via cp.async (reuse buffer) ----
    const __half* vb = g_v + headoff;
    for (int idx = tid; idx < 432*4; idx += 128) {
        int pix = idx >> 2, v = idx & 3;
        int hr = pix / 36, hc = pix - hr*36;
        int gi = i0 - 2 + hr, gj = j0 - 2 + hc;
        bool ok = ((unsigned)gi < HH) && ((unsigned)gj < WW);
        int cgi = ok ? gi : 0, cgj = ok ? gj : 0;
        __pipeline_memcpy_async(Hs + pix*SLD + v*8,
            vb + (size_t)(cgi*WW + cgj)*HDD + v*8, 16, ok ? 0 : 16);
    }
    __pipeline_commit();
    __pipeline_wait_prior(0);
    __syncthreads();

    // ---- V aggregation: two channel-halves, chunk-rotated loads ----
    __half* ag = g_agg + ((size_t)b*HWP + ij0)*CC + h*HDD;
#pragma unroll
    for (int ch = 0; ch < 2; ch++) {
        float out0[16], out1[16];
#pragma unroll
        for (int j=0;j<16;j++) { out0[j]=0.f; out1[j]=0.f; }
#pragma unroll
        for (int di=0; di<5; di++) {
            __half2 oa[8], ob[8];
#pragma unroll
            for (int j=0;j<8;j++) { oa[j]=__float2half2_rn(0.f); ob[j]=__float2half2_rn(0.f); }
#pragma unroll
            for (int djc=0; djc<6; djc++) {
                const __half* np = Hs + ((ty+di)*36 + (2*tx+djc))*SLD + ch*16;
                uint4 r0 = *(const uint4*)(np + ((0^rot)<<3));
                uint4 r1 = *(const uint4*)(np + ((1^rot)<<3));
                if (djc < 5) fma16(oa, __low2half2 (wh2[di*5+djc]),   r0, r1);
                if (djc > 0) fma16(ob, __high2half2(wh2[di*5+djc-1]), r0, r1);
            }
#pragma unroll
            for (int j=0;j<8;j++) {
                float2 fa = __half22float2(oa[j]);
                float2 fb = __half22float2(ob[j]);
                out0[2*j] += fa.x; out0[2*j+1] += fa.y;
                out1[2*j] += fb.x; out1[2*j+1] += fb.y;
            }
        }
#pragma unroll
        for (int v=0; v<2; v++) {
            uint2 h0 = f4toh4(make_float4(out0[v*8+0],out0[v*8+1],out0[v*8+2],out0[v*8+3]));
            uint2 h1 = f4toh4(make_float4(out0[v*8+4],out0[v*8+5],out0[v*8+6],out0[v*8+7]));
            *(uint4*)(ag + ch*16 + ((v^rot)<<3)) = make_uint4(h0.x,h0.y,h1.x,h1.y);
            uint2 g0 = f4toh4(make_float4(out1[v*8+0],out1[v*8+1],out1[v*8+2],out1[v*8+3]));
            uint2 g1 = f4toh4(make_float4(out1[v*8+4],out1[v*8+5],out1[v*8+6],out1[v*8+7]));
            *(uint4*)(ag + CC + ch*16 + ((v^rot)<<3)) = make_uint4(g0.x,g0.y,g1.x,g1.y);
        }
    }
}

// ============================================================
// Kernel 4: proj GEMM via WMMA fp16 + free BCHW transpose store.
// A staging via cp.async.
// ============================================================
#define PRJ_SMEM (16*132*4 + 2*128*LDH*2)   // 78080 B -> 2 blocks/SM

__global__ void __launch_bounds__(256, 2)
k_proj_wmma(const float* __restrict__ w_proj, const float* __restrict__ b_proj,
            float* __restrict__ out)
{
    extern __shared__ char smraw[];
    float*  bias_s = (float*)smraw;                    // [16][132]
    __half* As     = (__half*)(smraw + 16*132*4);      // [m=128][k=128] ld LDH
    __half* Bs     = As + 128*LDH;                     // [k=128][n=128] ld LDH

    const int tid = threadIdx.x;
    const int wid = tid >> 5;
    const int wm  = wid & 3;
    const int wn  = wid >> 2;
    const int p0  = blockIdx.x * 128;
    const int b   = p0 / HWP;
    const int ij0 = p0 % HWP;

    const __half* ab = g_agg + (size_t)p0 * CC;
#pragma unroll
    for (int it = 0; it < 8; it++) {
        int idx = tid + it*256;
        int m = idx >> 4, k8 = idx & 15;
        __pipeline_memcpy_async(As + m*LDH + k8*8,
                                ab + (size_t)m*CC + k8*8, 16, 0);
    }
    __pipeline_commit();
#pragma unroll
    for (int it = 0; it < 16; it++) {
        int idx = tid + it*256;
        int k = idx >> 5, n4 = idx & 31;
        *(uint2*)(Bs + k*LDH + n4*4) =
            f4toh4(*(const float4*)(w_proj + k*CC + n4*4));
    }
    if (tid < 128) {
        float bv = b_proj[tid];
#pragma unroll
        for (int r = 0; r < 16; r++) bias_s[r*132 + tid] = bv;
    }
    __pipeline_wait_prior(0);
    __syncthreads();

    wmma::fragment<wmma::accumulator, 16,16,16, float> acc[2][4];
#pragma unroll
    for (int mi = 0; mi < 2; mi++)
#pragma unroll
        for (int ni = 0; ni < 4; ni++)
            wmma::load_matrix_sync(acc[mi][ni], bias_s + wn*64 + ni*16,
                                   132, wmma::mem_row_major);

#pragma unroll
    for (int k0 = 0; k0 < CC; k0 += 16) {
        wmma::fragment<wmma::matrix_a, 16,16,16, __half, wmma::row_major> a[2];
#pragma unroll
        for (int mi = 0; mi < 2; mi++)
            wmma::load_matrix_sync(a[mi], As + (wm*32 + mi*16)*LDH + k0, LDH);
        wmma::fragment<wmma::matrix_b, 16,16,16, __half, wmma::row_major> bf[4];
#pragma unroll
        for (int ni = 0; ni < 4; ni++)
            wmma::load_matrix_sync(bf[ni], Bs + k0*LDH + wn*64 + ni*16, LDH);
#pragma unroll
        for (int mi = 0; mi < 2; mi++)
#pragma unroll
            for (int ni = 0; ni < 4; ni++)
                wmma::mma_sync(acc[mi][ni], a[mi], bf[ni], acc[mi][ni]);
    }

    float* ob = out + (size_t)b*CC*HWP + ij0;
#pragma unroll
    for (int mi = 0; mi < 2; mi++)
#pragma unroll
        for (int ni = 0; ni < 4; ni++) {
            int n0 = wn*64 + ni*16;
            int m0 = wm*32 + mi*16;
            wmma::store_matrix_sync(ob + (size_t)n0*HWP + m0, acc[mi][ni],
                                    HWP, wmma::mem_col_major);
        }
}

// ============================================================
extern "C" void kernel_launch(void* const* d_in, const int* in_sizes, int n_in,
                              void* d_out, int out_size)
{
    const float* x      = (const float*)d_in[0];
    const float* sims   = (const float*)d_in[1];
    const float* w_qk   = (const float*)d_in[2];
    const float* b_qk   = (const float*)d_in[3];
    const float* w_v    = (const float*)d_in[4];
    const float* b_v    = (const float*)d_in[5];
    const float* w_proj = (const float*)d_in[6];
    const float* b_proj = (const float*)d_in[7];
    float* out = (float*)d_out;

    cudaFuncSetAttribute(k_qkv_wmma,  cudaFuncAttributeMaxDynamicSharedMemorySize, QKV_SMEM);
    cudaFuncSetAttribute(k_pwd,       cudaFuncAttributeMaxDynamicSharedMemorySize, PWD_SMEM);
    cudaFuncSetAttribute(k_attn,      cudaFuncAttributeMaxDynamicSharedMemorySize, ATT_SMEM);
    cudaFuncSetAttribute(k_proj_wmma, cudaFuncAttributeMaxDynamicSharedMemorySize, PRJ_SMEM);

    k_qkv_wmma <<<NPIX/128, 256, QKV_SMEM>>>(x, w_qk, b_qk, w_v, b_v);
    k_pwd      <<<dim3(WW/32, HH/8, BB),      dim3(16,8), PWD_SMEM>>>(sims);
    k_attn     <<<dim3(WW/32, HH/8, BB*NHH),  dim3(16,8), ATT_SMEM>>>();
    k_proj_wmma<<<NPIX/128, 256, PRJ_SMEM>>>(w_proj, b_proj, out);
}

// round 16
// speedup vs baseline: 1.1260x; 1.0069x over previous
#include <cuda_runtime.h>
#include <cuda_pipeline.h>
#include <mma.h>
#include <cuda_fp16.h>
#include <math.h>

using namespace nvcuda;

#define BB 8
#define CC 128
#define HH 128
#define WW 128
#define NHH 4
#define HDD 32
#define SG2 256
#define HWP (HH*WW)      // 16384
#define NPIX (BB*HWP)    // 131072
#define KK2 25
#define SCALE 0.17677669529663687f   // 1/sqrt(32)

// ---- scratch (static device arrays; no runtime allocation) ----
static __device__ __align__(16) __half g_q[(size_t)NPIX*CC];
static __device__ __align__(16) __half g_k[(size_t)NPIX*CC];
static __device__ __align__(16) __half g_v[(size_t)NPIX*CC];
static __device__ __align__(16) __half g_agg[(size_t)NPIX*CC];
static __device__ __align__(16) __half g_pwd[(size_t)NPIX*KK2];  // x256 scale (cancels)
static __device__ __align__(16) __half g_wt[128*384];            // fp16 [k][q|k|v]
static __device__ __align__(16) __half g_wpt[128*128];           // fp16 [k][n]

#define LDH 136    // fp16 smem row stride for GEMMs (halfs)
#define SLD 40     // fp16 smem row stride for stencils (halfs) — 80 B = 5*16

__device__ __forceinline__ uint2 f4toh4(float4 v) {
    __half2 lo = __floats2half2_rn(v.x, v.y);
    __half2 hi = __floats2half2_rn(v.z, v.w);
    uint2 r;
    r.x = *(unsigned*)&lo;
    r.y = *(unsigned*)&hi;
    return r;
}

__device__ __forceinline__ float dot32v(const __half2* q2,
        uint4 r0, uint4 r1, uint4 r2, uint4 r3)
{
    __half2 a2 = __float2half2_rn(0.f);
    __half2 b2 = __float2half2_rn(0.f);
    a2 = __hfma2(q2[0],  *(__half2*)&r0.x, a2);
    b2 = __hfma2(q2[1],  *(__half2*)&r0.y, b2);
    a2 = __hfma2(q2[2],  *(__half2*)&r0.z, a2);
    b2 = __hfma2(q2[3],  *(__half2*)&r0.w, b2);
    a2 = __hfma2(q2[4],  *(__half2*)&r1.x, a2);
    b2 = __hfma2(q2[5],  *(__half2*)&r1.y, b2);
    a2 = __hfma2(q2[6],  *(__half2*)&r1.z, a2);
    b2 = __hfma2(q2[7],  *(__half2*)&r1.w, b2);
    a2 = __hfma2(q2[8],  *(__half2*)&r2.x, a2);
    b2 = __hfma2(q2[9],  *(__half2*)&r2.y, b2);
    a2 = __hfma2(q2[10], *(__half2*)&r2.z, a2);
    b2 = __hfma2(q2[11], *(__half2*)&r2.w, b2);
    a2 = __hfma2(q2[12], *(__half2*)&r3.x, a2);
    b2 = __hfma2(q2[13], *(__half2*)&r3.y, b2);
    a2 = __hfma2(q2[14], *(__half2*)&r3.z, a2);
    b2 = __hfma2(q2[15], *(__half2*)&r3.w, b2);
    float2 fa = __half22float2(a2);
    float2 fb = __half22float2(b2);
    return (fa.x + fa.y) + (fb.x + fb.y);
}

__device__ __forceinline__ void fma16(__half2* o, __half2 wk2, uint4 r0, uint4 r1)
{
    o[0] = __hfma2(wk2, *(__half2*)&r0.x, o[0]);
    o[1] = __hfma2(wk2, *(__half2*)&r0.y, o[1]);
    o[2] = __hfma2(wk2, *(__half2*)&r0.z, o[2]);
    o[3] = __hfma2(wk2, *(__half2*)&r0.w, o[3]);
    o[4] = __hfma2(wk2, *(__half2*)&r1.x, o[4]);
    o[5] = __hfma2(wk2, *(__half2*)&r1.y, o[5]);
    o[6] = __hfma2(wk2, *(__half2*)&r1.z, o[6]);
    o[7] = __hfma2(wk2, *(__half2*)&r1.w, o[7]);
}

// ============================================================
// Kernel 0: pre-convert weights to fp16 (65536 threads, ~2us).
// ============================================================
__global__ void k_prep(const float* __restrict__ w_qk, const float* __restrict__ w_v,
                       const float* __restrict__ w_proj)
{
    int i = blockIdx.x * 256 + threadIdx.x;
    if (i < 128*384) {
        int k = i / 384, n = i - k*384;
        float v = (n < 256) ? w_qk[k*256 + n] : w_v[k*128 + (n - 256)];
        g_wt[i] = __float2half(v);
    } else {
        g_wpt[i - 128*384] = __float2half(w_proj[i - 128*384]);
    }
}

// ============================================================
// Kernel 1: QKV GEMM via WMMA fp16; B tiles cp.async from g_wt.
// ============================================================
#define QKV_SMEM (16*132*4 + 2*128*LDH*2)   // 78080 B -> 2 blocks/SM

__global__ void __launch_bounds__(256, 2)
k_qkv_wmma(const float* __restrict__ x, const float* __restrict__ b_qk,
           const float* __restrict__ b_v)
{
    extern __shared__ char smraw[];
    float*  bias_s = (float*)smraw;                    // [16][132]
    __half* As     = (__half*)(smraw + 16*132*4);      // [k=128][m=128] ld LDH
    __half* Bs     = As + 128*LDH;                     // [k=128][n=128] ld LDH

    const int tid = threadIdx.x;
    const int wid = tid >> 5;
    const int wm  = wid & 3;
    const int wn  = wid >> 2;
    const int p0  = blockIdx.x * 128;
    const int b   = p0 / HWP;
    const int ij0 = p0 % HWP;
    const float* xb = x + (size_t)b*CC*HWP + ij0;

#pragma unroll
    for (int it = 0; it < 16; it++) {
        int idx = tid + it*256;
        int k = idx >> 5, m4 = idx & 31;
        *(uint2*)(As + k*LDH + m4*4) =
            f4toh4(*(const float4*)(xb + (size_t)k*HWP + m4*4));
    }

    for (int nt = 0; nt < 3; nt++) {
        __syncthreads();
        // B tile: raw fp16 cp.async from pre-converted g_wt
#pragma unroll
        for (int it = 0; it < 8; it++) {
            int idx = tid + it*256;          // 2048 16B chunks
            int k = idx >> 4, n8 = idx & 15;
            __pipeline_memcpy_async(Bs + k*LDH + n8*8,
                g_wt + k*384 + nt*128 + n8*8, 16, 0);
        }
        __pipeline_commit();
        if (tid < 128) {
            float bv = (nt < 2) ? b_qk[nt*128 + tid] : b_v[tid];
#pragma unroll
            for (int r = 0; r < 16; r++) bias_s[r*132 + tid] = bv;
        }
        __pipeline_wait_prior(0);
        __syncthreads();

        wmma::fragment<wmma::accumulator, 16,16,16, float> acc[2][4];
#pragma unroll
        for (int mi = 0; mi < 2; mi++)
#pragma unroll
            for (int ni = 0; ni < 4; ni++)
                wmma::load_matrix_sync(acc[mi][ni], bias_s + wn*64 + ni*16,
                                       132, wmma::mem_row_major);

#pragma unroll
        for (int k0 = 0; k0 < CC; k0 += 16) {
            wmma::fragment<wmma::matrix_a, 16,16,16, __half, wmma::col_major> a[2];
#pragma unroll
            for (int mi = 0; mi < 2; mi++)
                wmma::load_matrix_sync(a[mi], As + k0*LDH + wm*32 + mi*16, LDH);
            wmma::fragment<wmma::matrix_b, 16,16,16, __half, wmma::row_major> bf[4];
#pragma unroll
            for (int ni = 0; ni < 4; ni++)
                wmma::load_matrix_sync(bf[ni], Bs + k0*LDH + wn*64 + ni*16, LDH);
#pragma unroll
            for (int mi = 0; mi < 2; mi++)
#pragma unroll
                for (int ni = 0; ni < 4; ni++)
                    wmma::mma_sync(acc[mi][ni], a[mi], bf[ni], acc[mi][ni]);
        }

        __half* dstbase = (nt == 0) ? g_q : (nt == 1) ? g_k : g_v;
#pragma unroll
        for (int mi = 0; mi < 2; mi++)
#pragma unroll
            for (int ni = 0; ni < 4; ni++) {
                wmma::fragment<wmma::accumulator, 16,16,16, __half> hacc;
#pragma unroll
                for (int e = 0; e < 8; e++)
                    hacc.x[e] = __float2half(acc[mi][ni].x[e]);
                int n0 = wn*64 + ni*16;
                int head = n0 >> 5, d0 = n0 & 31;
                __half* dst = dstbase +
                    ((size_t)(b*NHH + head)*HWP + ij0 + wm*32 + mi*16)*HDD + d0;
                wmma::store_matrix_sync(dst, hacc, HDD, wmma::mem_row_major);
            }
    }
}

// ============================================================
// Kernel 2: pwd, pixel-paired + XOR chunk rotation. (R12/R15-proven.)
// ============================================================
#define PWD_SMEM (432*SLD*2)   // 34560 B

__global__ void __launch_bounds__(128, 4)
k_pwd(const float* __restrict__ sims)
{
    extern __shared__ __half Sh[];  // [432][40]
    const int b  = blockIdx.z;
    const int i0 = blockIdx.y * 8;
    const int j0 = blockIdx.x * 32;
    const int tx = threadIdx.x;     // 0..15
    const int ty = threadIdx.y;     // 0..7
    const int tid = ty*16 + tx;
    const int rot = (tx >> 2) & 1;
    const float* sb = sims + (size_t)b*HWP*SG2;

    float acc0[KK2], acc1[KK2];
#pragma unroll
    for (int k=0;k<KK2;k++) { acc0[k]=0.f; acc1[k]=0.f; }

    for (int scc = 0; scc < SG2; scc += 32) {
        __syncthreads();
        for (int idx = tid; idx < 432*4; idx += 128) {
            int pix = idx >> 2, v = idx & 3;
            int hr = pix / 36, hc = pix - hr*36;
            int gi = i0 - 2 + hr, gj = j0 - 2 + hc;
            uint4 o = make_uint4(0,0,0,0);
            if ((unsigned)gi < HH && (unsigned)gj < WW) {
                const float* src = sb + ((size_t)gi*WW + gj)*SG2 + scc + v*8;
                float4 f0 = *(const float4*)src;
                float4 f1 = *(const float4*)(src + 4);
                f0.x*=16.f; f0.y*=16.f; f0.z*=16.f; f0.w*=16.f;
                f1.x*=16.f; f1.y*=16.f; f1.z*=16.f; f1.w*=16.f;
                uint2 h0 = f4toh4(f0), h1 = f4toh4(f1);
                o = make_uint4(h0.x, h0.y, h1.x, h1.y);
            }
            *(uint4*)(Sh + pix*SLD + v*8) = o;
        }
        __syncthreads();

        __half2 oa[16], ob[16];
        {
            const __half* p0 = Sh + ((ty+2)*36 + (2*tx+2))*SLD;
#pragma unroll
            for (int v=0; v<4; v++) {
                uint4 r = *(const uint4*)(p0 + ((v^rot)<<3));
                oa[v*4+0]=*(__half2*)&r.x; oa[v*4+1]=*(__half2*)&r.y;
                oa[v*4+2]=*(__half2*)&r.z; oa[v*4+3]=*(__half2*)&r.w;
                uint4 s = *(const uint4*)(p0 + SLD + ((v^rot)<<3));
                ob[v*4+0]=*(__half2*)&s.x; ob[v*4+1]=*(__half2*)&s.y;
                ob[v*4+2]=*(__half2*)&s.z; ob[v*4+3]=*(__half2*)&s.w;
            }
        }
#pragma unroll
        for (int di=0; di<5; di++) {
#pragma unroll
            for (int djc=0; djc<6; djc++) {
                const __half* np = Sh + ((ty+di)*36 + (2*tx+djc))*SLD;
                uint4 r0 = *(const uint4*)(np + ((0^rot)<<3));
                uint4 r1 = *(const uint4*)(np + ((1^rot)<<3));
                uint4 r2 = *(const uint4*)(np + ((2^rot)<<3));
                uint4 r3 = *(const uint4*)(np + ((3^rot)<<3));
                if (djc < 5) acc0[di*5+djc]   += dot32v(oa, r0,r1,r2,r3);
                if (djc > 0) acc1[di*5+djc-1] += dot32v(ob, r0,r1,r2,r3);
            }
        }
    }
    const size_t p = (size_t)b*HWP + (size_t)(i0+ty)*WW + (j0+2*tx);
#pragma unroll
    for (int k=0;k<KK2;k++) {
        g_pwd[p*KK2 + k]     = __float2half(acc0[k]);
        g_pwd[(p+1)*KK2 + k] = __float2half(acc1[k]);
    }
}

// ============================================================
// Kernel 3: attention + V agg — all 4 heads per block (pwd L1-hot),
// cp.async staging, single K->V buffer per head, 4 blocks/SM.
// ============================================================
#define ATT_SMEM (432*SLD*2)   // 34560 B

__global__ void __launch_bounds__(128, 4)
k_attn()
{
    extern __shared__ __half Hs[];  // [432][40]: K then V, per head
    const int b  = blockIdx.z;
    const int i0 = blockIdx.y * 8;
    const int j0 = blockIdx.x * 32;
    const int tx = threadIdx.x;     // 0..15
    const int ty = threadIdx.y;     // 0..7
    const int tid = ty*16 + tx;
    const int rot = (tx >> 2) & 1;
    const int ij0 = (i0+ty)*WW + (j0 + 2*tx);
    const __half* pwp = g_pwd + ((size_t)b*HWP + ij0)*KK2;

    for (int h = 0; h < NHH; h++) {
        const size_t headoff = (size_t)(b*NHH + h)*HWP*HDD;

        // ---- stage K via cp.async ----
        const __half* kb = g_k + headoff;
        for (int idx = tid; idx < 432*4; idx += 128) {
            int pix = idx >> 2, v = idx & 3;
            int hr = pix / 36, hc = pix - hr*36;
            int gi = i0 - 2 + hr, gj = j0 - 2 + hc;
            bool ok = ((unsigned)gi < HH) && ((unsigned)gj < WW);
            int cgi = ok ? gi : 0, cgj = ok ? gj : 0;
            __pipeline_memcpy_async(Hs + pix*SLD + v*8,
                kb + (size_t)(cgi*WW + cgj)*HDD + v*8, 16, ok ? 0 : 16);
        }
        __pipeline_commit();

        // q pair (overlaps K copy)
        __half2 qa[16], qb[16];
        {
            const __half* qp = g_q + headoff + (size_t)ij0*HDD;
#pragma unroll
            for (int v=0; v<4; v++) {
                uint4 r = *(const uint4*)(qp + ((v^rot)<<3));
                qa[v*4+0]=*(__half2*)&r.x; qa[v*4+1]=*(__half2*)&r.y;
                qa[v*4+2]=*(__half2*)&r.z; qa[v*4+3]=*(__half2*)&r.w;
                uint4 s = *(const uint4*)(qp + HDD + ((v^rot)<<3));
                qb[v*4+0]=*(__half2*)&s.x; qb[v*4+1]=*(__half2*)&s.y;
                qb[v*4+2]=*(__half2*)&s.z; qb[v*4+3]=*(__half2*)&s.w;
            }
        }
        __pipeline_wait_prior(0);
        __syncthreads();

        // ---- scores; weights packed half2 ----
        __half2 wh2[KK2];
        float ssum0 = 0.f, ssum1 = 0.f;
#pragma unroll
        for (int di=0; di<5; di++) {
#pragma unroll
            for (int djc=0; djc<6; djc++) {
                const __half* np = Hs + ((ty+di)*36 + (2*tx+djc))*SLD;
                uint4 r0 = *(const uint4*)(np + ((0^rot)<<3));
                uint4 r1 = *(const uint4*)(np + ((1^rot)<<3));
                uint4 r2 = *(const uint4*)(np + ((2^rot)<<3));
                uint4 r3 = *(const uint4*)(np + ((3^rot)<<3));
                if (djc < 5) {
                    int kk = di*5+djc;
                    float s = dot32v(qa, r0,r1,r2,r3);
                    float w0 = __expf(s * SCALE) * __half2float(pwp[kk]);
                    ssum0 += w0;
                    wh2[kk] = __halves2half2(__float2half(w0), __float2half(0.f));
                }
                if (djc > 0) {
                    int kk = di*5+djc-1;
                    float s = dot32v(qb, r0,r1,r2,r3);
                    float w1 = __expf(s * SCALE) * __half2float(pwp[KK2+kk]);
                    ssum1 += w1;
                    wh2[kk] = __halves2half2(__low2half(wh2[kk]), __float2half(w1));
                }
            }
        }
        {
            __half2 inv2 = __floats2half2_rn(1.f / fmaxf(ssum0, 1e-30f),
                                             1.f / fmaxf(ssum1, 1e-30f));
#pragma unroll
            for (int k=0;k<KK2;k++) wh2[k] = __hmul2(wh2[k], inv2);
        }

        __syncthreads();   // done reading K

        // ---- stage V via cp.async (reuse buffer) ----
        const __half* vb = g_v + headoff;
        for (int idx = tid; idx < 432*4; idx += 128) {
            int pix = idx >> 2, v = idx & 3;
            int hr = pix / 36, hc = pix - hr*36;
            int gi = i0 - 2 + hr, gj = j0 - 2 + hc;
            bool ok = ((unsigned)gi < HH) && ((unsigned)gj < WW);
            int cgi = ok ? gi : 0, cgj = ok ? gj : 0;
            __pipeline_memcpy_async(Hs + pix*SLD + v*8,
                vb + (size_t)(cgi*WW + cgj)*HDD + v*8, 16, ok ? 0 : 16);
        }
        __pipeline_commit();
        __pipeline_wait_prior(0);
        __syncthreads();

        // ---- V aggregation: two channel-halves ----
        __half* ag = g_agg + ((size_t)b*HWP + ij0)*CC + h*HDD;
#pragma unroll
        for (int ch = 0; ch < 2; ch++) {
            float out0[16], out1[16];
#pragma unroll
            for (int j=0;j<16;j++) { out0[j]=0.f; out1[j]=0.f; }
#pragma unroll
            for (int di=0; di<5; di++) {
                __half2 oa[8], ob[8];
#pragma unroll
                for (int j=0;j<8;j++) { oa[j]=__float2half2_rn(0.f); ob[j]=__float2half2_rn(0.f); }
#pragma unroll
                for (int djc=0; djc<6; djc++) {
                    const __half* np = Hs + ((ty+di)*36 + (2*tx+djc))*SLD + ch*16;
                    uint4 r0 = *(const uint4*)(np + ((0^rot)<<3));
                    uint4 r1 = *(const uint4*)(np + ((1^rot)<<3));
                    if (djc < 5) fma16(oa, __low2half2 (wh2[di*5+djc]),   r0, r1);
                    if (djc > 0) fma16(ob, __high2half2(wh2[di*5+djc-1]), r0, r1);
                }
#pragma unroll
                for (int j=0;j<8;j++) {
                    float2 fa = __half22float2(oa[j]);
                    float2 fb = __half22float2(ob[j]);
                    out0[2*j] += fa.x; out0[2*j+1] += fa.y;
                    out1[2*j] += fb.x; out1[2*j+1] += fb.y;
                }
            }
#pragma unroll
            for (int v=0; v<2; v++) {
                uint2 h0 = f4toh4(make_float4(out0[v*8+0],out0[v*8+1],out0[v*8+2],out0[v*8+3]));
                uint2 h1 = f4toh4(make_float4(out0[v*8+4],out0[v*8+5],out0[v*8+6],out0[v*8+7]));
                *(uint4*)(ag + ch*16 + ((v^rot)<<3)) = make_uint4(h0.x,h0.y,h1.x,h1.y);
                uint2 g0 = f4toh4(make_float4(out1[v*8+0],out1[v*8+1],out1[v*8+2],out1[v*8+3]));
                uint2 g1 = f4toh4(make_float4(out1[v*8+4],out1[v*8+5],out1[v*8+6],out1[v*8+7]));
                *(uint4*)(ag + CC + ch*16 + ((v^rot)<<3)) = make_uint4(g0.x,g0.y,g1.x,g1.y);
            }
        }
        __syncthreads();   // buffer free for next head
    }
}

// ============================================================
// Kernel 4: proj GEMM via WMMA fp16 + free BCHW transpose store.
// A and B staged via cp.async (B from pre-converted g_wpt).
// ============================================================
#define PRJ_SMEM (16*132*4 + 2*128*LDH*2)   // 78080 B -> 2 blocks/SM

__global__ void __launch_bounds__(256, 2)
k_proj_wmma(const float* __restrict__ b_proj, float* __restrict__ out)
{
    extern __shared__ char smraw[];
    float*  bias_s = (float*)smraw;                    // [16][132]
    __half* As     = (__half*)(smraw + 16*132*4);      // [m=128][k=128] ld LDH
    __half* Bs     = As + 128*LDH;                     // [k=128][n=128] ld LDH

    const int tid = threadIdx.x;
    const int wid = tid >> 5;
    const int wm  = wid & 3;
    const int wn  = wid >> 2;
    const int p0  = blockIdx.x * 128;
    const int b   = p0 / HWP;
    const int ij0 = p0 % HWP;

    const __half* ab = g_agg + (size_t)p0 * CC;
#pragma unroll
    for (int it = 0; it < 8; it++) {
        int idx = tid + it*256;
        int m = idx >> 4, k8 = idx & 15;
        __pipeline_memcpy_async(As + m*LDH + k8*8,
                                ab + (size_t)m*CC + k8*8, 16, 0);
    }
#pragma unroll
    for (int it = 0; it < 8; it++) {
        int idx = tid + it*256;
        int k = idx >> 4, n8 = idx & 15;
        __pipeline_memcpy_async(Bs + k*LDH + n8*8,
                                g_wpt + k*128 + n8*8, 16, 0);
    }
    __pipeline_commit();
    if (tid < 128) {
        float bv = b_proj[tid];
#pragma unroll
        for (int r = 0; r < 16; r++) bias_s[r*132 + tid] = bv;
    }
    __pipeline_wait_prior(0);
    __syncthreads();

    wmma::fragment<wmma::accumulator, 16,16,16, float> acc[2][4];
#pragma unroll
    for (int mi = 0; mi < 2; mi++)
#pragma unroll
        for (int ni = 0; ni < 4; ni++)
            wmma::load_matrix_sync(acc[mi][ni], bias_s + wn*64 + ni*16,
                                   132, wmma::mem_row_major);

#pragma unroll
    for (int k0 = 0; k0 < CC; k0 += 16) {
        wmma::fragment<wmma::matrix_a, 16,16,16, __half, wmma::row_major> a[2];
#pragma unroll
        for (int mi = 0; mi < 2; mi++)
            wmma::load_matrix_sync(a[mi], As + (wm*32 + mi*16)*LDH + k0, LDH);
        wmma::fragment<wmma::matrix_b, 16,16,16, __half, wmma::row_major> bf[4];
#pragma unroll
        for (int ni = 0; ni < 4; ni++)
            wmma::load_matrix_sync(bf[ni], Bs + k0*LDH + wn*64 + ni*16, LDH);
#pragma unroll
        for (int mi = 0; mi < 2; mi++)
#pragma unroll
            for (int ni = 0; ni < 4; ni++)
                wmma::mma_sync(acc[mi][ni], a[mi], bf[ni], acc[mi][ni]);
    }

    float* ob = out + (size_t)b*CC*HWP + ij0;
#pragma unroll
    for (int mi = 0; mi < 2; mi++)
#pragma unroll
        for (int ni = 0; ni < 4; ni++) {
            int n0 = wn*64 + ni*16;
            int m0 = wm*32 + mi*16;
            wmma::store_matrix_sync(ob + (size_t)n0*HWP + m0, acc[mi][ni],
                                    HWP, wmma::mem_col_major);
        }
}

// ============================================================
extern "C" void kernel_launch(void* const* d_in, const int* in_sizes, int n_in,
                              void* d_out, int out_size)
{
    const float* x      = (const float*)d_in[0];
    const float* sims   = (const float*)d_in[1];
    const float* w_qk   = (const float*)d_in[2];
    const float* b_qk   = (const float*)d_in[3];
    const float* w_v    = (const float*)d_in[4];
    const float* b_v    = (const float*)d_in[5];
    const float* w_proj = (const float*)d_in[6];
    const float* b_proj = (const float*)d_in[7];
    float* out = (float*)d_out;

    cudaFuncSetAttribute(k_qkv_wmma,  cudaFuncAttributeMaxDynamicSharedMemorySize, QKV_SMEM);
    cudaFuncSetAttribute(k_pwd,       cudaFuncAttributeMaxDynamicSharedMemorySize, PWD_SMEM);
    cudaFuncSetAttribute(k_attn,      cudaFuncAttributeMaxDynamicSharedMemorySize, ATT_SMEM);
    cudaFuncSetAttribute(k_proj_wmma, cudaFuncAttributeMaxDynamicSharedMemorySize, PRJ_SMEM);

    k_prep     <<<256, 256>>>(w_qk, w_v, w_proj);
    k_qkv_wmma <<<NPIX/128, 256, QKV_SMEM>>>(x, b_qk, b_v);
    k_pwd      <<<dim3(WW/32, HH/8, BB),  dim3(16,8), PWD_SMEM>>>(sims);
    k_attn     <<<dim3(WW/32, HH/8, BB),  dim3(16,8), ATT_SMEM>>>();
    k_proj_wmma<<<NPIX/128, 256, PRJ_SMEM>>>(b_proj, out);
}